// round 2
// baseline (speedup 1.0000x reference)
#include <cuda_runtime.h>

#define Tn 48
#define Sn 2048
#define Bn 256

__device__ float g_fwd[Bn];
__device__ float g_gold[Bn];

// ---------------------------------------------------------------------------
// Forward algorithm in linear domain with per-step rescaling.
// One block per batch element. Thread j (0..47) owns output state j and keeps
// column j of E = exp(transitions) in registers. Current scaled alpha (Q) is
// broadcast through double-buffered shared memory; exactly one __syncthreads
// per time step. Thread 0 tracks the log-magnitude M with Kahan compensation.
// Invariant at top of step i: alpha_{i-1}[k] = M + log(r * Q[k]),
// where Q = sP[cur], r = sZ[cur] (= ~1/Q[0]).
// ---------------------------------------------------------------------------
__global__ __launch_bounds__(64)
void crf_forward_kernel(const float* __restrict__ emis,
                        const int*   __restrict__ mask,
                        const float* __restrict__ trans,
                        const float* __restrict__ startT,
                        const float* __restrict__ endT)
{
    __shared__ __align__(16) float sP[2][64];
    __shared__ float sZ[2];
    __shared__ float sRed[64];

    const int b = blockIdx.x;
    const int j = threadIdx.x;
    const bool act = (j < Tn);
    const int jj = act ? j : 0;

    // E column for this thread: E[k][j] = exp(trans[k][j])
    float Ecol[Tn];
    #pragma unroll
    for (int k = 0; k < Tn; ++k)
        Ecol[k] = __expf(trans[k * Tn + jj]);

    const float* em_b = emis + (size_t)b * Sn * Tn;
    const int*   mk_b = mask + (size_t)b * Sn;

    // init: alpha0 = start + emissions[:,0]
    float Q0 = __expf(startT[jj] + em_b[jj]);
    if (act) sP[0][j] = Q0;
    float Mlog = 0.f, comp = 0.f;
    if (j == 0) {
        sZ[0] = __frcp_rn(Q0);
        Mlog  = __logf(Q0);
    }

    // prefetch pipeline (distance 4) for emission value and mask
    float e0 = em_b[1 * Tn + jj];
    float e1 = em_b[2 * Tn + jj];
    float e2 = em_b[3 * Tn + jj];
    float e3 = em_b[4 * Tn + jj];
    int   m0 = mk_b[1], m1 = mk_b[2], m2 = mk_b[3], m3 = mk_b[4];

    __syncthreads();

    int cur = 0;
    #pragma unroll 4
    for (int i = 1; i < Sn; ++i) {
        const float em = e0;
        const int   mi = m0;
        e0 = e1; e1 = e2; e2 = e3;
        m0 = m1; m1 = m2; m2 = m3;
        const int ip = (i + 4 < Sn) ? (i + 4) : (Sn - 1);
        e3 = em_b[(size_t)ip * Tn + jj];
        m3 = mk_b[ip];

        if (mi) {  // mask is uniform across the block (same address)
            const float F = __expf(em);
            const float r = sZ[cur];
            const float4* p4 = (const float4*)sP[cur];
            float a0 = 0.f, a1 = 0.f, a2 = 0.f, a3 = 0.f;
            #pragma unroll
            for (int kk = 0; kk < 12; ++kk) {
                const float4 q = p4[kk];
                a0 = fmaf(q.x, Ecol[4 * kk + 0], a0);
                a1 = fmaf(q.y, Ecol[4 * kk + 1], a1);
                a2 = fmaf(q.z, Ecol[4 * kk + 2], a2);
                a3 = fmaf(q.w, Ecol[4 * kk + 3], a3);
            }
            const float Ssum = (a0 + a1) + (a2 + a3);
            const float Qn = Ssum * F * r;
            const int nxt = cur ^ 1;
            if (act) sP[nxt][j] = Qn;
            if (j == 0) {
                sZ[nxt] = __frcp_rn(Qn);
                // Kahan: Mlog += log(Qn[0])
                const float t = __logf(Qn) - comp;
                const float s = Mlog + t;
                comp = (s - Mlog) - t;
                Mlog = s;
            }
            cur = nxt;
            __syncthreads();
        }
    }

    // finalize: fwd = M + log(r * sum_j Q[j]*exp(end[j]))
    const float r = sZ[cur];
    const float v = act ? sP[cur][j] * __expf(endT[jj]) : 0.f;
    sRed[threadIdx.x] = v;
    __syncthreads();
    if (j == 0) {
        float tot = 0.f;
        #pragma unroll
        for (int k = 0; k < Tn; ++k) tot += sRed[k];
        g_fwd[b] = Mlog + logf(r * tot);
    }
}

// ---------------------------------------------------------------------------
// Gold path score: one block per batch, strided gather + block reduce.
// tags may arrive as int32 (JAX silently downgrades int64 without x64 mode)
// or as genuine int64. Sniff the layout: for little-endian int64 with values
// in [0,48), every odd 32-bit word is zero; for int32 random tags in [0,48)
// that is (1/48)^32-impossible. Deterministic given fixed inputs.
// ---------------------------------------------------------------------------
__global__ __launch_bounds__(256)
void crf_gold_kernel(const float* __restrict__ emis,
                     const int*   __restrict__ tags32,
                     const int*   __restrict__ mask,
                     const float* __restrict__ trans,
                     const float* __restrict__ startT,
                     const float* __restrict__ endT)
{
    __shared__ double sred[256];
    __shared__ int    scnt[256];
    __shared__ int    s_is64;
    const int b = blockIdx.x, t = threadIdx.x;

    // dtype sniff on the first 32 candidate high-words of the whole buffer
    if (t < 32) {
        unsigned hw = (unsigned)tags32[2 * t + 1];
        #pragma unroll
        for (int off = 16; off > 0; off >>= 1)
            hw |= __shfl_down_sync(0xffffffffu, hw, off);
        if (t == 0) s_is64 = (hw == 0u) ? 1 : 0;
    }
    __syncthreads();
    const int is64 = s_is64;
    const size_t base = (size_t)b * Sn;

    const int*   mk = mask + base;
    const float* em = emis + (size_t)b * Sn * Tn;

    double acc = 0.0;
    int cnt = 0;
    for (int i = t; i < Sn; i += 256) {
        const int m = mk[i];
        cnt += m;
        if (i >= 1 && m) {
            const size_t ic = base + (size_t)i;
            const int tp = is64 ? tags32[(ic - 1) << 1] : tags32[ic - 1];
            const int tc = is64 ? tags32[ic << 1]       : tags32[ic];
            acc += (double)trans[tp * Tn + tc] + (double)em[(size_t)i * Tn + tc];
        }
    }
    sred[t] = acc;
    scnt[t] = cnt;
    __syncthreads();
    for (int s2 = 128; s2 > 0; s2 >>= 1) {
        if (t < s2) { sred[t] += sred[t + s2]; scnt[t] += scnt[t + s2]; }
        __syncthreads();
    }
    if (t == 0) {
        const int t0 = is64 ? tags32[base << 1] : tags32[base];
        double g = sred[0] + (double)startT[t0] + (double)em[t0];
        const size_t il = base + (size_t)(scnt[0] - 1);
        const int tl = is64 ? tags32[il << 1] : tags32[il];
        g += (double)endT[tl];
        g_gold[b] = (float)g;
    }
}

// ---------------------------------------------------------------------------
// Final: out = mean(fwd - gold)
// ---------------------------------------------------------------------------
__global__ __launch_bounds__(256)
void crf_final_kernel(float* __restrict__ out)
{
    __shared__ double sred[256];
    const int t = threadIdx.x;
    sred[t] = (double)g_fwd[t] - (double)g_gold[t];
    __syncthreads();
    for (int s2 = 128; s2 > 0; s2 >>= 1) {
        if (t < s2) sred[t] += sred[t + s2];
        __syncthreads();
    }
    if (t == 0) out[0] = (float)(sred[0] / (double)Bn);
}

extern "C" void kernel_launch(void* const* d_in, const int* in_sizes, int n_in,
                              void* d_out, int out_size)
{
    const float* emis   = (const float*)d_in[0];
    const int*   tags32 = (const int*)d_in[1];   // int32 OR int64 viewed as words
    const int*   mask   = (const int*)d_in[2];
    const float* trans  = (const float*)d_in[3];
    const float* startT = (const float*)d_in[4];
    const float* endT   = (const float*)d_in[5];
    float* out = (float*)d_out;

    crf_forward_kernel<<<Bn, 64>>>(emis, mask, trans, startT, endT);
    crf_gold_kernel<<<Bn, 256>>>(emis, tags32, mask, trans, startT, endT);
    crf_final_kernel<<<1, 256>>>(out);
}

// round 3
// speedup vs baseline: 1.7364x; 1.7364x over previous
#include <cuda_runtime.h>

#define Tn 48
#define Sn 2048
#define Bn 256

__device__ float g_fwd[Bn];
__device__ float g_gold[Bn];

// ---------------------------------------------------------------------------
// Forward algorithm, linear domain, exponent-only rescaling.
// One block (64 threads) per batch. Thread j owns output state j and holds
// column j of E = exp(transitions) in registers. Raw scaled alpha S is
// double-buffered in shared memory; ONE unconditional __syncthreads per step.
//
// Invariant: true alpha_i[k] = Esum*ln2 + log(S_i[k]).
// Per step: every thread extracts e = ilogb(S[0]) and r = 2^-e from the
// broadcast q0 (3 integer ops, exact), folds r into the emission factor
// (scalar commutes out of the sum), and thread 0 accumulates the integer
// exponent. No MUFU log/rcp in the loop; no branches (mask via select).
// ---------------------------------------------------------------------------
__global__ __launch_bounds__(64)
void crf_forward_kernel(const float* __restrict__ emis,
                        const int*   __restrict__ mask,
                        const float* __restrict__ trans,
                        const float* __restrict__ startT,
                        const float* __restrict__ endT)
{
    __shared__ __align__(16) float sP[2][64];
    __shared__ float sRed[64];

    const int b = blockIdx.x;
    const int j = threadIdx.x;
    const bool act = (j < Tn);
    const int jj = act ? j : 0;

    // E column for this thread: E[k][j] = exp(trans[k][j])
    float Ecol[Tn];
    #pragma unroll
    for (int k = 0; k < Tn; ++k)
        Ecol[k] = __expf(trans[k * Tn + jj]);

    const float* em_b = emis + (size_t)b * Sn * Tn;
    const int*   mk_b = mask + (size_t)b * Sn;

    // init: S_0 = exp(start + emissions[:,0]), stored raw
    const float S0 = __expf(startT[jj] + em_b[jj]);
    sP[0][j] = S0;                // lanes 48-63 write clones of lane 0; never read
    int Esum = 0;

    // prefetch pipeline (distance 4) for emission value and mask
    float e0 = em_b[1 * Tn + jj];
    float e1 = em_b[2 * Tn + jj];
    float e2 = em_b[3 * Tn + jj];
    float e3 = em_b[4 * Tn + jj];
    int   m0 = mk_b[1], m1 = mk_b[2], m2 = mk_b[3], m3 = mk_b[4];

    __syncthreads();

    int cur = 0;
    #pragma unroll 2
    for (int i = 1; i < Sn; ++i) {
        const float em = e0;
        const int   mi = m0;
        e0 = e1; e1 = e2; e2 = e3;
        m0 = m1; m1 = m2; m2 = m3;
        const int ip = (i + 4 < Sn) ? (i + 4) : (Sn - 1);
        e3 = em_b[(size_t)ip * Tn + jj];
        m3 = mk_b[ip];

        // broadcast normalizer source + own old value (selects, off chain)
        const float q0   = sP[cur][0];
        const float qown = sP[cur][j];

        // r = 2^-ilogb(q0): pure integer ops, exact
        const int  xb = __float_as_int(q0) >> 23;      // biased exponent
        const int  eX = xb - 127;
        const float r = __int_as_float((254 - xb) << 23);
        const float Fr = __expf(em) * r;               // hides under FMA chain

        const float4* p4 = (const float4*)sP[cur];
        float a0 = 0.f, a1 = 0.f, a2 = 0.f, a3 = 0.f;
        #pragma unroll
        for (int kk = 0; kk < 12; ++kk) {
            const float4 q = p4[kk];
            a0 = fmaf(q.x, Ecol[4 * kk + 0], a0);
            a1 = fmaf(q.y, Ecol[4 * kk + 1], a1);
            a2 = fmaf(q.z, Ecol[4 * kk + 2], a2);
            a3 = fmaf(q.w, Ecol[4 * kk + 3], a3);
        }
        const float Ssum = (a0 + a1) + (a2 + a3);
        const float Qn   = Ssum * Fr;

        const int nxt = cur ^ 1;
        sP[nxt][j] = mi ? Qn : qown;          // branchless mask
        if (j == 0) Esum += mi ? eX : 0;      // exact integer magnitude
        cur = nxt;
        __syncthreads();
    }

    // finalize: fwd = Esum*ln2 + log(sum_j S[j]*exp(end[j]))
    const float v = act ? sP[cur][j] * __expf(endT[jj]) : 0.f;
    sRed[j] = v;
    __syncthreads();
    if (j == 0) {
        float tot = 0.f;
        #pragma unroll
        for (int k = 0; k < Tn; ++k) tot += sRed[k];
        g_fwd[b] = (float)((double)Esum * 0.6931471805599453
                           + (double)logf(tot));
    }
}

// ---------------------------------------------------------------------------
// Gold path score: one block per batch, strided gather + block reduce.
// tags may arrive as int32 (JAX silently downgrades int64 without x64 mode)
// or as genuine int64 — sniff the layout (odd 32-bit words all zero => int64).
// ---------------------------------------------------------------------------
__global__ __launch_bounds__(256)
void crf_gold_kernel(const float* __restrict__ emis,
                     const int*   __restrict__ tags32,
                     const int*   __restrict__ mask,
                     const float* __restrict__ trans,
                     const float* __restrict__ startT,
                     const float* __restrict__ endT)
{
    __shared__ double sred[256];
    __shared__ int    scnt[256];
    __shared__ int    s_is64;
    const int b = blockIdx.x, t = threadIdx.x;

    if (t < 32) {
        unsigned hw = (unsigned)tags32[2 * t + 1];
        #pragma unroll
        for (int off = 16; off > 0; off >>= 1)
            hw |= __shfl_down_sync(0xffffffffu, hw, off);
        if (t == 0) s_is64 = (hw == 0u) ? 1 : 0;
    }
    __syncthreads();
    const int is64 = s_is64;
    const size_t base = (size_t)b * Sn;

    const int*   mk = mask + base;
    const float* em = emis + (size_t)b * Sn * Tn;

    double acc = 0.0;
    int cnt = 0;
    for (int i = t; i < Sn; i += 256) {
        const int m = mk[i];
        cnt += m;
        if (i >= 1 && m) {
            const size_t ic = base + (size_t)i;
            const int tp = is64 ? tags32[(ic - 1) << 1] : tags32[ic - 1];
            const int tc = is64 ? tags32[ic << 1]       : tags32[ic];
            acc += (double)trans[tp * Tn + tc] + (double)em[(size_t)i * Tn + tc];
        }
    }
    sred[t] = acc;
    scnt[t] = cnt;
    __syncthreads();
    for (int s2 = 128; s2 > 0; s2 >>= 1) {
        if (t < s2) { sred[t] += sred[t + s2]; scnt[t] += scnt[t + s2]; }
        __syncthreads();
    }
    if (t == 0) {
        const int t0 = is64 ? tags32[base << 1] : tags32[base];
        double g = sred[0] + (double)startT[t0] + (double)em[t0];
        const size_t il = base + (size_t)(scnt[0] - 1);
        const int tl = is64 ? tags32[il << 1] : tags32[il];
        g += (double)endT[tl];
        g_gold[b] = (float)g;
    }
}

// ---------------------------------------------------------------------------
// Final: out = mean(fwd - gold)
// ---------------------------------------------------------------------------
__global__ __launch_bounds__(256)
void crf_final_kernel(float* __restrict__ out)
{
    __shared__ double sred[256];
    const int t = threadIdx.x;
    sred[t] = (double)g_fwd[t] - (double)g_gold[t];
    __syncthreads();
    for (int s2 = 128; s2 > 0; s2 >>= 1) {
        if (t < s2) sred[t] += sred[t + s2];
        __syncthreads();
    }
    if (t == 0) out[0] = (float)(sred[0] / (double)Bn);
}

extern "C" void kernel_launch(void* const* d_in, const int* in_sizes, int n_in,
                              void* d_out, int out_size)
{
    const float* emis   = (const float*)d_in[0];
    const int*   tags32 = (const int*)d_in[1];   // int32 OR int64 viewed as words
    const int*   mask   = (const int*)d_in[2];
    const float* trans  = (const float*)d_in[3];
    const float* startT = (const float*)d_in[4];
    const float* endT   = (const float*)d_in[5];
    float* out = (float*)d_out;

    crf_forward_kernel<<<Bn, 64>>>(emis, mask, trans, startT, endT);
    crf_gold_kernel<<<Bn, 256>>>(emis, tags32, mask, trans, startT, endT);
    crf_final_kernel<<<1, 256>>>(out);
}